// round 3
// baseline (speedup 1.0000x reference)
#include <cuda_runtime.h>

#define NN 50000
#define NE 800000
#define NG 512
#define HID 128
#define EIN 64

// Scratch (device globals: allocation-free rule)
__device__ float g_bufA[NN * HID];   // aggr / MLP input
__device__ float g_bufB[NN * HID];   // MLP hidden
__device__ float g_bufC[NN * HID];   // layer output
__device__ float g_pool[NG * HID];   // pooled per-graph features

// ---- packed f32x2 helpers (FFMA2 path, sm_103a) ----------------------------
__device__ __forceinline__ unsigned long long pk2(float v) {
    unsigned long long r;
    asm("mov.b64 %0, {%1, %1};" : "=l"(r) : "f"(v));
    return r;
}
__device__ __forceinline__ unsigned long long ffma2(unsigned long long a,
                                                    unsigned long long b,
                                                    unsigned long long c) {
    unsigned long long d;
    asm("fma.rn.f32x2 %0, %1, %2, %3;" : "=l"(d) : "l"(a), "l"(b), "l"(c));
    return d;
}
__device__ __forceinline__ float2 upk(unsigned long long v) {
    float2 f;
    asm("mov.b64 {%0, %1}, %2;" : "=f"(f.x), "=f"(f.y) : "l"(v));
    return f;
}

// ---------------------------------------------------------------------------
__global__ void copy_kernel(const float4* __restrict__ s, float4* __restrict__ d, int n) {
    int i = blockIdx.x * blockDim.x + threadIdx.x;
    int stride = gridDim.x * blockDim.x;
    for (; i < n; i += stride) d[i] = s[i];
}

// ---------------------------------------------------------------------------
// Fused edge kernel: aggr[dst] += relu(x[src] + attr @ W + b)
// aggr pre-initialized with the residual (x). Warp handles 8 edges/iter;
// lane owns columns [lane*4, lane*4+4) held as two packed f32x2 accumulators.
__global__ void edge_kernel(const float* __restrict__ xin,
                            const float* __restrict__ eattr,
                            const int* __restrict__ ei,         // [2, NE] int32
                            const float* __restrict__ W,        // [64,128]
                            const float* __restrict__ bias,     // [128]
                            float* __restrict__ aggr) {
    extern __shared__ float sh[];
    float* sW = sh;                     // 64*128 = 8192 floats
    float* sattr = sh + EIN * HID;      // 8 warps * 8 edges * 64 = 4096 floats
    int tid = threadIdx.x;
    for (int i = tid; i < EIN * HID; i += blockDim.x) sW[i] = W[i];
    __syncthreads();

    int warp = tid >> 5, lane = tid & 31;
    ulonglong2 bb = *(const ulonglong2*)(bias + lane * 4);
    float* sat = sattr + warp * (8 * EIN);

    int gw = blockIdx.x * 8 + warp;
    int nw = gridDim.x * 8;
    const int* src = ei;
    const int* dst = ei + NE;

    for (int base = gw * 8; base < NE; base += nw * 8) {
        __syncwarp();
        #pragma unroll
        for (int e = 0; e < 8; e++) {
            int eid = base + e;
            if (eid < NE) {
                const float* ap = eattr + (size_t)eid * EIN;
                sat[e * EIN + lane]      = ap[lane];
                sat[e * EIN + lane + 32] = ap[lane + 32];
            }
        }
        __syncwarp();

        unsigned long long acc0[8], acc1[8];
        #pragma unroll
        for (int e = 0; e < 8; e++) { acc0[e] = bb.x; acc1[e] = bb.y; }

        #pragma unroll 4
        for (int k = 0; k < EIN; k++) {
            ulonglong2 wv = *(const ulonglong2*)&sW[k * HID + lane * 4];
            #pragma unroll
            for (int e = 0; e < 8; e++) {
                unsigned long long aa = pk2(sat[e * EIN + k]);
                acc0[e] = ffma2(aa, wv.x, acc0[e]);
                acc1[e] = ffma2(aa, wv.y, acc1[e]);
            }
        }

        #pragma unroll
        for (int e = 0; e < 8; e++) {
            int eid = base + e;
            if (eid >= NE) break;
            int sI = src[eid], dI = dst[eid];
            float4 xv = *(const float4*)(xin + (size_t)sI * HID + lane * 4);
            float2 lo = upk(acc0[e]), hi = upk(acc1[e]);
            float4 m;
            m.x = fmaxf(xv.x + lo.x, 0.f);
            m.y = fmaxf(xv.y + lo.y, 0.f);
            m.z = fmaxf(xv.z + hi.x, 0.f);
            m.w = fmaxf(xv.w + hi.y, 0.f);
            atomicAdd((float4*)(aggr + (size_t)dI * HID + lane * 4), m);
        }
    }
}

// ---------------------------------------------------------------------------
// C[M,128] = act(A[M,128] @ W[128,128] + bias), optional relu.
// Block tile 64x128, 256 threads, micro-tile 8 rows x 4 cols (2 f32x2 each).
__global__ void gemm128_kernel(const float* __restrict__ A,
                               const float* __restrict__ W,
                               const float* __restrict__ bias,
                               float* __restrict__ C,
                               int M, int doRelu) {
    __shared__ float sA[64 * 32];
    __shared__ float sB[32 * 128];
    int tid = threadIdx.x;
    int tr = tid >> 5, tc = tid & 31;
    int brow = blockIdx.x * 64;

    unsigned long long acc0[8], acc1[8];
    #pragma unroll
    for (int i = 0; i < 8; i++) { acc0[i] = 0ull; acc1[i] = 0ull; }

    for (int kb = 0; kb < 4; kb++) {
        // load A tile 64x32
        int lin = tid * 8;
        int ar = lin >> 5, ac = lin & 31;
        int grow = brow + ar;
        float4 z = make_float4(0.f, 0.f, 0.f, 0.f);
        const float* ap = A + (size_t)grow * HID + kb * 32 + ac;
        float4 v0 = (grow < M) ? *(const float4*)ap : z;
        float4 v1 = (grow < M) ? *(const float4*)(ap + 4) : z;
        *(float4*)&sA[lin]     = v0;
        *(float4*)&sA[lin + 4] = v1;
        // load B tile 32x128
        int lb = tid * 16;
        int br = lb >> 7, bc = lb & 127;
        const float* wp = W + (size_t)(kb * 32 + br) * HID + bc;
        *(float4*)&sB[lb]      = *(const float4*)wp;
        *(float4*)&sB[lb + 4]  = *(const float4*)(wp + 4);
        *(float4*)&sB[lb + 8]  = *(const float4*)(wp + 8);
        *(float4*)&sB[lb + 12] = *(const float4*)(wp + 12);
        __syncthreads();

        #pragma unroll 4
        for (int kk = 0; kk < 32; kk++) {
            ulonglong2 bv = *(const ulonglong2*)&sB[kk * HID + tc * 4];
            #pragma unroll
            for (int i = 0; i < 8; i++) {
                unsigned long long aa = pk2(sA[(tr * 8 + i) * 32 + kk]);
                acc0[i] = ffma2(aa, bv.x, acc0[i]);
                acc1[i] = ffma2(aa, bv.y, acc1[i]);
            }
        }
        __syncthreads();
    }

    float4 bb = *(const float4*)(bias + tc * 4);
    #pragma unroll
    for (int i = 0; i < 8; i++) {
        int row = brow + tr * 8 + i;
        if (row < M) {
            float2 lo = upk(acc0[i]), hi = upk(acc1[i]);
            float4 o;
            o.x = lo.x + bb.x;
            o.y = lo.y + bb.y;
            o.z = hi.x + bb.z;
            o.w = hi.y + bb.w;
            if (doRelu) {
                o.x = fmaxf(o.x, 0.f); o.y = fmaxf(o.y, 0.f);
                o.z = fmaxf(o.z, 0.f); o.w = fmaxf(o.w, 0.f);
            }
            *(float4*)&C[(size_t)row * HID + tc * 4] = o;
        }
    }
}

// ---------------------------------------------------------------------------
// Atomic-free mean pool: batch is sorted, binary-search per-graph bounds.
__global__ void pool_kernel(const float* __restrict__ h,
                            const int* __restrict__ batch,
                            float* __restrict__ pool) {
    __shared__ int bounds[2];
    int g = blockIdx.x, t = threadIdx.x;  // 128 threads
    if (t < 2) {
        int target = g + t;
        int lo = 0, hi = NN;
        while (lo < hi) {
            int mid = (lo + hi) >> 1;
            if (batch[mid] < target) lo = mid + 1; else hi = mid;
        }
        bounds[t] = lo;
    }
    __syncthreads();
    int lo = bounds[0], hi = bounds[1];
    float s = 0.f;
    for (int n = lo; n < hi; n++) s += h[(size_t)n * HID + t];
    float cnt = (float)((hi - lo) > 1 ? (hi - lo) : 1);
    pool[g * HID + t] = s / cnt;
}

// ---------------------------------------------------------------------------
// s = relu(g @ fc_w + fc_b); 3 linear heads of width 1.
__global__ void head_kernel(const float* __restrict__ pool,
                            const float* __restrict__ fcw, const float* __restrict__ fcb,
                            const float* __restrict__ hSw, const float* __restrict__ hSb,
                            const float* __restrict__ hPw, const float* __restrict__ hPb,
                            const float* __restrict__ hNw, const float* __restrict__ hNb,
                            float* __restrict__ out) {
    __shared__ float sg[HID];
    __shared__ float red[3][2];
    int g = blockIdx.x, t = threadIdx.x;  // 64 threads
    sg[t]      = pool[g * HID + t];
    sg[t + 64] = pool[g * HID + t + 64];
    __syncthreads();
    float a = fcb[t];
    #pragma unroll 4
    for (int k = 0; k < HID; k++) a = fmaf(sg[k], fcw[k * 64 + t], a);
    float s = fmaxf(a, 0.f);
    float pS = s * hSw[t], pP = s * hPw[t], pN = s * hNw[t];
    #pragma unroll
    for (int off = 16; off; off >>= 1) {
        pS += __shfl_down_sync(0xffffffffu, pS, off);
        pP += __shfl_down_sync(0xffffffffu, pP, off);
        pN += __shfl_down_sync(0xffffffffu, pN, off);
    }
    int warp = t >> 5, lane = t & 31;
    if (lane == 0) { red[0][warp] = pS; red[1][warp] = pP; red[2][warp] = pN; }
    __syncthreads();
    if (t == 0) {
        out[g]            = red[0][0] + red[0][1] + hSb[0];
        out[NG + g]       = red[1][0] + red[1][1] + hPb[0];
        out[2 * NG + g]   = red[2][0] + red[2][1] + hNb[0];
    }
}

// ---------------------------------------------------------------------------
extern "C" void kernel_launch(void* const* d_in, const int* in_sizes, int n_in,
                              void* d_out, int out_size) {
    const float* x     = (const float*)d_in[0];
    const int*   ei    = (const int*)d_in[1];
    const float* eattr = (const float*)d_in[2];
    const int*   batch = (const int*)d_in[3];
    const float *e1w = (const float*)d_in[4],  *e1b = (const float*)d_in[5];
    const float *n1w1 = (const float*)d_in[6], *n1b1 = (const float*)d_in[7];
    const float *n1w2 = (const float*)d_in[8], *n1b2 = (const float*)d_in[9];
    const float *e2w = (const float*)d_in[10], *e2b = (const float*)d_in[11];
    const float *n2w1 = (const float*)d_in[12], *n2b1 = (const float*)d_in[13];
    const float *n2w2 = (const float*)d_in[14], *n2b2 = (const float*)d_in[15];
    const float *fcw = (const float*)d_in[16], *fcb = (const float*)d_in[17];
    const float *hSw = (const float*)d_in[18], *hSb = (const float*)d_in[19];
    const float *hPw = (const float*)d_in[20], *hPb = (const float*)d_in[21];
    const float *hNw = (const float*)d_in[22], *hNb = (const float*)d_in[23];
    float* out = (float*)d_out;

    void *pA, *pB, *pC, *pP;
    cudaGetSymbolAddress(&pA, g_bufA);
    cudaGetSymbolAddress(&pB, g_bufB);
    cudaGetSymbolAddress(&pC, g_bufC);
    cudaGetSymbolAddress(&pP, g_pool);
    float* A = (float*)pA; float* B = (float*)pB;
    float* C = (float*)pC; float* P = (float*)pP;

    const int n4 = NN * HID / 4;
    const int smem_edge = (EIN * HID + 8 * 8 * EIN) * sizeof(float);  // 49152 B
    const int gemm_blocks = (NN + 63) / 64;

    // ----- Layer 1 -----
    copy_kernel<<<4096, 256>>>((const float4*)x, (float4*)A, n4);
    edge_kernel<<<592, 256, smem_edge>>>(x, eattr, ei, e1w, e1b, A);
    gemm128_kernel<<<gemm_blocks, 256>>>(A, n1w1, n1b1, B, NN, 1);
    gemm128_kernel<<<gemm_blocks, 256>>>(B, n1w2, n1b2, C, NN, 1);

    // ----- Layer 2 -----
    copy_kernel<<<4096, 256>>>((const float4*)C, (float4*)A, n4);
    edge_kernel<<<592, 256, smem_edge>>>(C, eattr, ei, e2w, e2b, A);
    gemm128_kernel<<<gemm_blocks, 256>>>(A, n2w1, n2b1, B, NN, 1);
    gemm128_kernel<<<gemm_blocks, 256>>>(B, n2w2, n2b2, C, NN, 1);

    // ----- Pool + heads -----
    pool_kernel<<<NG, HID>>>(C, batch, P);
    head_kernel<<<NG, 64>>>(P, fcw, fcb, hSw, hSb, hPw, hPb, hNw, hNb, out);
}

// round 4
// speedup vs baseline: 1.1038x; 1.1038x over previous
#include <cuda_runtime.h>

#define NN 50000
#define NE 800000
#define NG 512
#define HID 128
#define EIN 64

typedef unsigned long long ull;

// Scratch (device globals: allocation-free rule)
__device__ float g_bufA[NN * HID];   // aggr / MLP input
__device__ float g_bufB[NN * HID];   // MLP hidden
__device__ float g_bufC[NN * HID];   // layer output
__device__ float g_pool[NG * HID];   // pooled per-graph features

// ---- packed f32x2 helpers (sm_103a) ---------------------------------------
__device__ __forceinline__ ull pk2(float v) {
    ull r;
    asm("mov.b64 %0, {%1, %1};" : "=l"(r) : "f"(v));
    return r;
}
__device__ __forceinline__ ull ffma2(ull a, ull b, ull c) {
    ull d;
    asm("fma.rn.f32x2 %0, %1, %2, %3;" : "=l"(d) : "l"(a), "l"(b), "l"(c));
    return d;
}
__device__ __forceinline__ float2 upk(ull v) {
    float2 f;
    asm("mov.b64 {%0, %1}, %2;" : "=f"(f.x), "=f"(f.y) : "l"(v));
    return f;
}

// ---------------------------------------------------------------------------
__global__ void copy_kernel(const float4* __restrict__ s, float4* __restrict__ d, int n) {
    int i = blockIdx.x * blockDim.x + threadIdx.x;
    int stride = gridDim.x * blockDim.x;
    for (; i < n; i += stride) d[i] = s[i];
}

// ---------------------------------------------------------------------------
// Fused edge kernel: aggr[dst] += relu(x[src] + attr @ W + b)
// aggr pre-initialized with residual x. Warp handles 8 edges/iter.
// Staged attr tile is TRANSPOSED: sat_t[k][e], row stride 10 floats (pad).
// Accumulators packed f32x2 over EDGE PAIRS: acc[p][c], p=edge pair, c=col.
// Lane owns cols [lane*4, lane*4+4).
#define SAT_STRIDE 10
__global__ void edge_kernel(const float* __restrict__ xin,
                            const float* __restrict__ eattr,
                            const int* __restrict__ ei,         // [2, NE] int32
                            const float* __restrict__ W,        // [64,128]
                            const float* __restrict__ bias,     // [128]
                            float* __restrict__ aggr) {
    extern __shared__ float sh[];
    float* sW = sh;                                  // 64*128 floats = 32KB
    float* sat = sh + EIN * HID;                     // 8 warps * 64*10 floats
    int tid = threadIdx.x;
    for (int i = tid; i < EIN * HID; i += blockDim.x) sW[i] = W[i];
    __syncthreads();

    int warp = tid >> 5, lane = tid & 31;
    float4 bb = *(const float4*)(bias + lane * 4);
    ull bb2[4] = { pk2(bb.x), pk2(bb.y), pk2(bb.z), pk2(bb.w) };
    float* sat_w = sat + warp * (EIN * SAT_STRIDE);

    int gw = blockIdx.x * 8 + warp;
    int nw = gridDim.x * 8;
    const int* src = ei;
    const int* dst = ei + NE;

    for (int base = gw * 8; base < NE; base += nw * 8) {
        __syncwarp();
        // stage transposed: sat_w[k*10 + e] = attr[base+e][k]
        #pragma unroll
        for (int e = 0; e < 8; e++) {
            int eid = base + e;
            if (eid < NE) {
                const float* ap = eattr + (size_t)eid * EIN;
                float v0 = ap[lane];
                float v1 = ap[lane + 32];
                sat_w[lane * SAT_STRIDE + e] = v0;
                sat_w[(lane + 32) * SAT_STRIDE + e] = v1;
            }
        }
        __syncwarp();

        ull acc[4][4];
        #pragma unroll
        for (int p = 0; p < 4; p++)
            #pragma unroll
            for (int c = 0; c < 4; c++) acc[p][c] = bb2[c];

        #pragma unroll 8
        for (int k = 0; k < EIN; k++) {
            const float* sr = sat_w + k * SAT_STRIDE;
            ull a01 = *(const ull*)(sr + 0);
            ull a23 = *(const ull*)(sr + 2);
            ull a45 = *(const ull*)(sr + 4);
            ull a67 = *(const ull*)(sr + 6);
            float4 wv = *(const float4*)&sW[k * HID + lane * 4];
            ull w0 = pk2(wv.x), w1 = pk2(wv.y), w2 = pk2(wv.z), w3 = pk2(wv.w);
            acc[0][0] = ffma2(a01, w0, acc[0][0]);
            acc[0][1] = ffma2(a01, w1, acc[0][1]);
            acc[0][2] = ffma2(a01, w2, acc[0][2]);
            acc[0][3] = ffma2(a01, w3, acc[0][3]);
            acc[1][0] = ffma2(a23, w0, acc[1][0]);
            acc[1][1] = ffma2(a23, w1, acc[1][1]);
            acc[1][2] = ffma2(a23, w2, acc[1][2]);
            acc[1][3] = ffma2(a23, w3, acc[1][3]);
            acc[2][0] = ffma2(a45, w0, acc[2][0]);
            acc[2][1] = ffma2(a45, w1, acc[2][1]);
            acc[2][2] = ffma2(a45, w2, acc[2][2]);
            acc[2][3] = ffma2(a45, w3, acc[2][3]);
            acc[3][0] = ffma2(a67, w0, acc[3][0]);
            acc[3][1] = ffma2(a67, w1, acc[3][1]);
            acc[3][2] = ffma2(a67, w2, acc[3][2]);
            acc[3][3] = ffma2(a67, w3, acc[3][3]);
        }

        #pragma unroll
        for (int p = 0; p < 4; p++) {
            float2 c0 = upk(acc[p][0]);
            float2 c1 = upk(acc[p][1]);
            float2 c2 = upk(acc[p][2]);
            float2 c3 = upk(acc[p][3]);
            int e0 = base + 2 * p;
            int e1 = e0 + 1;
            if (e0 < NE) {
                int sI = src[e0], dI = dst[e0];
                float4 xv = *(const float4*)(xin + (size_t)sI * HID + lane * 4);
                float4 m;
                m.x = fmaxf(xv.x + c0.x, 0.f);
                m.y = fmaxf(xv.y + c1.x, 0.f);
                m.z = fmaxf(xv.z + c2.x, 0.f);
                m.w = fmaxf(xv.w + c3.x, 0.f);
                atomicAdd((float4*)(aggr + (size_t)dI * HID + lane * 4), m);
            }
            if (e1 < NE) {
                int sI = src[e1], dI = dst[e1];
                float4 xv = *(const float4*)(xin + (size_t)sI * HID + lane * 4);
                float4 m;
                m.x = fmaxf(xv.x + c0.y, 0.f);
                m.y = fmaxf(xv.y + c1.y, 0.f);
                m.z = fmaxf(xv.z + c2.y, 0.f);
                m.w = fmaxf(xv.w + c3.y, 0.f);
                atomicAdd((float4*)(aggr + (size_t)dI * HID + lane * 4), m);
            }
        }
    }
}

// ---------------------------------------------------------------------------
// C[M,128] = act(A[M,128] @ W[128,128] + bias), optional relu.
// Block tile 64x128, 256 threads. A tile staged TRANSPOSED: sAt[kk][row],
// row stride 66 (pad). Accumulators packed f32x2 over row pairs.
#define SAT_G 66
__global__ void gemm128_kernel(const float* __restrict__ A,
                               const float* __restrict__ W,
                               const float* __restrict__ bias,
                               float* __restrict__ C,
                               int M, int doRelu) {
    __shared__ float sAt[32 * SAT_G];   // transposed A tile [kk][row]
    __shared__ float sB[32 * 128];
    int tid = threadIdx.x;
    int tr = tid >> 5, tc = tid & 31;   // warp=row group, lane=col group
    int brow = blockIdx.x * 64;

    ull acc[4][4];
    #pragma unroll
    for (int p = 0; p < 4; p++)
        #pragma unroll
        for (int c = 0; c < 4; c++) acc[p][c] = 0ull;

    for (int kb = 0; kb < 4; kb++) {
        // load A tile 64 rows x 32 k, store transposed
        int lin = tid * 8;
        int ar = lin >> 5, ac = lin & 31;    // ar: row in tile, ac: k offset
        int grow = brow + ar;
        float4 z = make_float4(0.f, 0.f, 0.f, 0.f);
        const float* ap = A + (size_t)grow * HID + kb * 32 + ac;
        float4 v0 = (grow < M) ? *(const float4*)ap : z;
        float4 v1 = (grow < M) ? *(const float4*)(ap + 4) : z;
        sAt[(ac + 0) * SAT_G + ar] = v0.x;
        sAt[(ac + 1) * SAT_G + ar] = v0.y;
        sAt[(ac + 2) * SAT_G + ar] = v0.z;
        sAt[(ac + 3) * SAT_G + ar] = v0.w;
        sAt[(ac + 4) * SAT_G + ar] = v1.x;
        sAt[(ac + 5) * SAT_G + ar] = v1.y;
        sAt[(ac + 6) * SAT_G + ar] = v1.z;
        sAt[(ac + 7) * SAT_G + ar] = v1.w;
        // load B tile 32x128
        int lb = tid * 16;
        int br = lb >> 7, bc = lb & 127;
        const float* wp = W + (size_t)(kb * 32 + br) * HID + bc;
        *(float4*)&sB[lb]      = *(const float4*)wp;
        *(float4*)&sB[lb + 4]  = *(const float4*)(wp + 4);
        *(float4*)&sB[lb + 8]  = *(const float4*)(wp + 8);
        *(float4*)&sB[lb + 12] = *(const float4*)(wp + 12);
        __syncthreads();

        #pragma unroll 8
        for (int kk = 0; kk < 32; kk++) {
            const float* sr = sAt + kk * SAT_G + tr * 8;
            ull a01 = *(const ull*)(sr + 0);
            ull a23 = *(const ull*)(sr + 2);
            ull a45 = *(const ull*)(sr + 4);
            ull a67 = *(const ull*)(sr + 6);
            float4 wv = *(const float4*)&sB[kk * HID + tc * 4];
            ull w0 = pk2(wv.x), w1 = pk2(wv.y), w2 = pk2(wv.z), w3 = pk2(wv.w);
            acc[0][0] = ffma2(a01, w0, acc[0][0]);
            acc[0][1] = ffma2(a01, w1, acc[0][1]);
            acc[0][2] = ffma2(a01, w2, acc[0][2]);
            acc[0][3] = ffma2(a01, w3, acc[0][3]);
            acc[1][0] = ffma2(a23, w0, acc[1][0]);
            acc[1][1] = ffma2(a23, w1, acc[1][1]);
            acc[1][2] = ffma2(a23, w2, acc[1][2]);
            acc[1][3] = ffma2(a23, w3, acc[1][3]);
            acc[2][0] = ffma2(a45, w0, acc[2][0]);
            acc[2][1] = ffma2(a45, w1, acc[2][1]);
            acc[2][2] = ffma2(a45, w2, acc[2][2]);
            acc[2][3] = ffma2(a45, w3, acc[2][3]);
            acc[3][0] = ffma2(a67, w0, acc[3][0]);
            acc[3][1] = ffma2(a67, w1, acc[3][1]);
            acc[3][2] = ffma2(a67, w2, acc[3][2]);
            acc[3][3] = ffma2(a67, w3, acc[3][3]);
        }
        __syncthreads();
    }

    float4 bbv = *(const float4*)(bias + tc * 4);
    #pragma unroll
    for (int p = 0; p < 4; p++) {
        float2 c0 = upk(acc[p][0]);
        float2 c1 = upk(acc[p][1]);
        float2 c2 = upk(acc[p][2]);
        float2 c3 = upk(acc[p][3]);
        int r0 = brow + tr * 8 + 2 * p;
        int r1 = r0 + 1;
        if (r0 < M) {
            float4 o;
            o.x = c0.x + bbv.x; o.y = c1.x + bbv.y;
            o.z = c2.x + bbv.z; o.w = c3.x + bbv.w;
            if (doRelu) {
                o.x = fmaxf(o.x, 0.f); o.y = fmaxf(o.y, 0.f);
                o.z = fmaxf(o.z, 0.f); o.w = fmaxf(o.w, 0.f);
            }
            *(float4*)&C[(size_t)r0 * HID + tc * 4] = o;
        }
        if (r1 < M) {
            float4 o;
            o.x = c0.y + bbv.x; o.y = c1.y + bbv.y;
            o.z = c2.y + bbv.z; o.w = c3.y + bbv.w;
            if (doRelu) {
                o.x = fmaxf(o.x, 0.f); o.y = fmaxf(o.y, 0.f);
                o.z = fmaxf(o.z, 0.f); o.w = fmaxf(o.w, 0.f);
            }
            *(float4*)&C[(size_t)r1 * HID + tc * 4] = o;
        }
    }
}

// ---------------------------------------------------------------------------
// Atomic-free mean pool: batch is sorted, binary-search per-graph bounds.
__global__ void pool_kernel(const float* __restrict__ h,
                            const int* __restrict__ batch,
                            float* __restrict__ pool) {
    __shared__ int bounds[2];
    int g = blockIdx.x, t = threadIdx.x;  // 128 threads
    if (t < 2) {
        int target = g + t;
        int lo = 0, hi = NN;
        while (lo < hi) {
            int mid = (lo + hi) >> 1;
            if (batch[mid] < target) lo = mid + 1; else hi = mid;
        }
        bounds[t] = lo;
    }
    __syncthreads();
    int lo = bounds[0], hi = bounds[1];
    float s = 0.f;
    for (int n = lo; n < hi; n++) s += h[(size_t)n * HID + t];
    float cnt = (float)((hi - lo) > 1 ? (hi - lo) : 1);
    pool[g * HID + t] = s / cnt;
}

// ---------------------------------------------------------------------------
// s = relu(g @ fc_w + fc_b); 3 linear heads of width 1.
__global__ void head_kernel(const float* __restrict__ pool,
                            const float* __restrict__ fcw, const float* __restrict__ fcb,
                            const float* __restrict__ hSw, const float* __restrict__ hSb,
                            const float* __restrict__ hPw, const float* __restrict__ hPb,
                            const float* __restrict__ hNw, const float* __restrict__ hNb,
                            float* __restrict__ out) {
    __shared__ float sg[HID];
    __shared__ float red[3][2];
    int g = blockIdx.x, t = threadIdx.x;  // 64 threads
    sg[t]      = pool[g * HID + t];
    sg[t + 64] = pool[g * HID + t + 64];
    __syncthreads();
    float a = fcb[t];
    #pragma unroll 4
    for (int k = 0; k < HID; k++) a = fmaf(sg[k], fcw[k * 64 + t], a);
    float s = fmaxf(a, 0.f);
    float pS = s * hSw[t], pP = s * hPw[t], pN = s * hNw[t];
    #pragma unroll
    for (int off = 16; off; off >>= 1) {
        pS += __shfl_down_sync(0xffffffffu, pS, off);
        pP += __shfl_down_sync(0xffffffffu, pP, off);
        pN += __shfl_down_sync(0xffffffffu, pN, off);
    }
    int warp = t >> 5, lane = t & 31;
    if (lane == 0) { red[0][warp] = pS; red[1][warp] = pP; red[2][warp] = pN; }
    __syncthreads();
    if (t == 0) {
        out[g]            = red[0][0] + red[0][1] + hSb[0];
        out[NG + g]       = red[1][0] + red[1][1] + hPb[0];
        out[2 * NG + g]   = red[2][0] + red[2][1] + hNb[0];
    }
}

// ---------------------------------------------------------------------------
extern "C" void kernel_launch(void* const* d_in, const int* in_sizes, int n_in,
                              void* d_out, int out_size) {
    const float* x     = (const float*)d_in[0];
    const int*   ei    = (const int*)d_in[1];
    const float* eattr = (const float*)d_in[2];
    const int*   batch = (const int*)d_in[3];
    const float *e1w = (const float*)d_in[4],  *e1b = (const float*)d_in[5];
    const float *n1w1 = (const float*)d_in[6], *n1b1 = (const float*)d_in[7];
    const float *n1w2 = (const float*)d_in[8], *n1b2 = (const float*)d_in[9];
    const float *e2w = (const float*)d_in[10], *e2b = (const float*)d_in[11];
    const float *n2w1 = (const float*)d_in[12], *n2b1 = (const float*)d_in[13];
    const float *n2w2 = (const float*)d_in[14], *n2b2 = (const float*)d_in[15];
    const float *fcw = (const float*)d_in[16], *fcb = (const float*)d_in[17];
    const float *hSw = (const float*)d_in[18], *hSb = (const float*)d_in[19];
    const float *hPw = (const float*)d_in[20], *hPb = (const float*)d_in[21];
    const float *hNw = (const float*)d_in[22], *hNb = (const float*)d_in[23];
    float* out = (float*)d_out;

    void *pA, *pB, *pC, *pP;
    cudaGetSymbolAddress(&pA, g_bufA);
    cudaGetSymbolAddress(&pB, g_bufB);
    cudaGetSymbolAddress(&pC, g_bufC);
    cudaGetSymbolAddress(&pP, g_pool);
    float* A = (float*)pA; float* B = (float*)pB;
    float* C = (float*)pC; float* P = (float*)pP;

    const int n4 = NN * HID / 4;
    // sW (64*128) + 8 warps * 64*SAT_STRIDE floats
    const int smem_edge = (EIN * HID + 8 * EIN * SAT_STRIDE) * sizeof(float);  // 53248 B
    static int smem_set = 0;
    if (!smem_set) {
        cudaFuncSetAttribute(edge_kernel, cudaFuncAttributeMaxDynamicSharedMemorySize, smem_edge);
        smem_set = 1;
    }
    const int gemm_blocks = (NN + 63) / 64;

    // ----- Layer 1 -----
    copy_kernel<<<4096, 256>>>((const float4*)x, (float4*)A, n4);
    edge_kernel<<<592, 256, smem_edge>>>(x, eattr, ei, e1w, e1b, A);
    gemm128_kernel<<<gemm_blocks, 256>>>(A, n1w1, n1b1, B, NN, 1);
    gemm128_kernel<<<gemm_blocks, 256>>>(B, n1w2, n1b2, C, NN, 1);

    // ----- Layer 2 -----
    copy_kernel<<<4096, 256>>>((const float4*)C, (float4*)A, n4);
    edge_kernel<<<592, 256, smem_edge>>>(C, eattr, ei, e2w, e2b, A);
    gemm128_kernel<<<gemm_blocks, 256>>>(A, n2w1, n2b1, B, NN, 1);
    gemm128_kernel<<<gemm_blocks, 256>>>(B, n2w2, n2b2, C, NN, 1);

    // ----- Pool + heads -----
    pool_kernel<<<NG, HID>>>(C, batch, P);
    head_kernel<<<NG, 64>>>(P, fcw, fcb, hSw, hSb, hPw, hPb, hNw, hNb, out);
}